// round 13
// baseline (speedup 1.0000x reference)
#include <cuda_runtime.h>
#include <cuda_fp16.h>
#include <cstdint>
#include <math.h>

#define NN 50000
#define EE 600000
#define DD 128
#define GG 128

// ---------------- device scratch ----------------
__device__ __half g_x16[NN * DD];      // fp16 input x (L0 gather + residual)
__device__ __half g_h0[NN * DD];       // L0 out
__device__ __half g_h1[NN * DD];       // L1 out
__device__ __half g_h2[NN * DD];       // L2 out (pool input)
__device__ __half g_xa16[NN * DD];     // aggregation scratch
__device__ int    g_deg[NN];
__device__ int    g_rank[EE];
__device__ float  g_dinv[NN];
__device__ int    g_rowptr[NN + 1];
__device__ int    g_csrc[EE];
__device__ float  g_cw[EE];
__device__ __half g_wt16[3][DD * 144]; // W^T fp16, row stride 144, perm16 k-layout

__device__ __forceinline__ float4 h4tof4(uint2 raw) {
    __half2 h0 = *(__half2*)&raw.x;
    __half2 h1 = *(__half2*)&raw.y;
    float2 f0 = __half22float2(h0);
    float2 f1 = __half22float2(h1);
    return make_float4(f0.x, f0.y, f1.x, f1.y);
}
__device__ __forceinline__ uint2 f4toh4(float a, float b, float c, float d) {
    __half2 p0 = __floats2half2_rn(a, b);
    __half2 p1 = __floats2half2_rn(c, d);
    uint2 st;
    st.x = *(uint32_t*)&p0;
    st.y = *(uint32_t*)&p1;
    return st;
}
__device__ __forceinline__ void ldmatrix_x4(uint32_t& r0, uint32_t& r1,
                                            uint32_t& r2, uint32_t& r3, uint32_t addr) {
    asm volatile("ldmatrix.sync.aligned.m8n8.x4.shared.b16 {%0,%1,%2,%3}, [%4];"
                 : "=r"(r0), "=r"(r1), "=r"(r2), "=r"(r3) : "r"(addr));
}
__device__ __forceinline__ void mma_f16(float c[4], const uint32_t a[4], const uint32_t b[2]) {
    asm volatile(
        "mma.sync.aligned.m16n8k16.row.col.f32.f16.f16.f32 "
        "{%0,%1,%2,%3}, {%4,%5,%6,%7}, {%8,%9}, {%0,%1,%2,%3};"
        : "+f"(c[0]), "+f"(c[1]), "+f"(c[2]), "+f"(c[3])
        : "r"(a[0]), "r"(a[1]), "r"(a[2]), "r"(a[3]), "r"(b[0]), "r"(b[1]));
}

// ======================= deg + x->fp16 convert =======================
#define DEGB ((EE + 255) / 256)
#define CVTB ((NN * DD / 8 + 255) / 256)

__global__ void k_deg_x16(const int* __restrict__ ei, const float* __restrict__ x) {
    if (blockIdx.x < DEGB) {
        int e = blockIdx.x * 256 + threadIdx.x;
        if (e < EE) g_rank[e] = atomicAdd(&g_deg[ei[EE + e]], 1);
    } else {
        int i = (blockIdx.x - DEGB) * 256 + threadIdx.x;
        if (i < NN * DD / 8) {
            float4 v0 = *(const float4*)(x + (size_t)i * 8);
            float4 v1 = *(const float4*)(x + (size_t)i * 8 + 4);
            uint2 a = f4toh4(v0.x, v0.y, v0.z, v0.w);
            uint2 b = f4toh4(v1.x, v1.y, v1.z, v1.w);
            *(uint4*)(g_x16 + (size_t)i * 8) = make_uint4(a.x, a.y, b.x, b.y);
        }
    }
}

// ======================= scan + dinv + W^T fp16 precompute =======================
__global__ void k_scan_wt(const float* __restrict__ W0, const float* __restrict__ W1,
                          const float* __restrict__ W2) {
    if (blockIdx.x > 0) {
        const float* Ws[3] = {W0, W1, W2};
        int l = blockIdx.x - 1;
        for (int i = threadIdx.x; i < DD * 144; i += 1024) {
            int n = i / 144;
            int j = i % 144;
            __half v = __float2half(0.f);
            if (j < 128) {
                int grp = j >> 4, w = j & 15;
                int k = grp * 16 + ((w >> 1) & 1) * 8 + (w >> 2) * 2 + (w & 1);
                v = __float2half(Ws[l][(size_t)k * DD + n]);
            }
            g_wt16[l][i] = v;
        }
        return;
    }
    const int CH = (NN + 1023) / 1024;
    __shared__ int ss[1024];
    int t = threadIdx.x;
    int vals[CH];
    int base = t * CH;
    int loc = 0;
#pragma unroll
    for (int i = 0; i < CH; ++i) {
        int idx = base + i;
        int v = (idx < NN) ? g_deg[idx] : 0;
        if (idx < NN) g_dinv[idx] = rsqrtf((float)(v + 1));
        vals[i] = loc;
        loc += v;
    }
    ss[t] = loc;
    __syncthreads();
    for (int off = 1; off < 1024; off <<= 1) {
        int v = (t >= off) ? ss[t - off] : 0;
        __syncthreads();
        ss[t] += v;
        __syncthreads();
    }
    int pre = (t > 0) ? ss[t - 1] : 0;
#pragma unroll
    for (int i = 0; i < CH; ++i) {
        int idx = base + i;
        if (idx < NN) g_rowptr[idx] = pre + vals[i];
    }
    if (t == 1023) g_rowptr[NN] = ss[1023];
}

__global__ void k_fill(const int* __restrict__ ei) {
    int e = blockIdx.x * blockDim.x + threadIdx.x;
    if (e < EE) {
        int s = ei[e];
        int d = ei[EE + e];
        int pos = g_rowptr[d] + g_rank[e];
        g_csrc[pos] = s;
        g_cw[pos] = g_dinv[s] * g_dinv[d];
    }
}

// ======================= aggregation: one warp per node, meta prefetch =======================
__global__ void __launch_bounds__(256) k_agg(const __half* __restrict__ a16,
                                             __half* __restrict__ xa16) {
    int w = (blockIdx.x * blockDim.x + threadIdx.x) >> 5;
    int lane = threadIdx.x & 31;
    if (w >= NN) return;
    int col = lane * 4;

    int e0 = g_rowptr[w], e1 = g_rowptr[w + 1];
    float di = g_dinv[w];
    float sw = di * di;
    float4 a0 = h4tof4(*(const uint2*)(a16 + (size_t)w * DD + col));
    a0.x *= sw; a0.y *= sw; a0.z *= sw; a0.w *= sw;
    float4 a1 = make_float4(0.f, 0.f, 0.f, 0.f);
    float4 a2 = a1, a3 = a1;

    int nfull = (e1 - e0) >> 2;
    int e = e0;
    if (nfull > 0) {
        // prologue: meta for block 0
        int s0 = __ldg(&g_csrc[e + 0]);
        int s1 = __ldg(&g_csrc[e + 1]);
        int s2 = __ldg(&g_csrc[e + 2]);
        int s3 = __ldg(&g_csrc[e + 3]);
        float w0 = __ldg(&g_cw[e + 0]);
        float w1 = __ldg(&g_cw[e + 1]);
        float w2 = __ldg(&g_cw[e + 2]);
        float w3 = __ldg(&g_cw[e + 3]);
        for (int blk = 0; blk < nfull; ++blk) {
            int en = e + 4;
            // prefetch next block's meta BEFORE consuming current gathers
            int t0 = 0, t1 = 0, t2 = 0, t3 = 0;
            float u0 = 0.f, u1 = 0.f, u2 = 0.f, u3 = 0.f;
            if (blk + 1 < nfull) {
                t0 = __ldg(&g_csrc[en + 0]);
                t1 = __ldg(&g_csrc[en + 1]);
                t2 = __ldg(&g_csrc[en + 2]);
                t3 = __ldg(&g_csrc[en + 3]);
                u0 = __ldg(&g_cw[en + 0]);
                u1 = __ldg(&g_cw[en + 1]);
                u2 = __ldg(&g_cw[en + 2]);
                u3 = __ldg(&g_cw[en + 3]);
            }
            float4 h0 = h4tof4(*(const uint2*)(a16 + (size_t)s0 * DD + col));
            float4 h1 = h4tof4(*(const uint2*)(a16 + (size_t)s1 * DD + col));
            float4 h2 = h4tof4(*(const uint2*)(a16 + (size_t)s2 * DD + col));
            float4 h3 = h4tof4(*(const uint2*)(a16 + (size_t)s3 * DD + col));
            a0.x += w0 * h0.x; a0.y += w0 * h0.y; a0.z += w0 * h0.z; a0.w += w0 * h0.w;
            a1.x += w1 * h1.x; a1.y += w1 * h1.y; a1.z += w1 * h1.z; a1.w += w1 * h1.w;
            a2.x += w2 * h2.x; a2.y += w2 * h2.y; a2.z += w2 * h2.z; a2.w += w2 * h2.w;
            a3.x += w3 * h3.x; a3.y += w3 * h3.y; a3.z += w3 * h3.z; a3.w += w3 * h3.w;
            s0 = t0; s1 = t1; s2 = t2; s3 = t3;
            w0 = u0; w1 = u1; w2 = u2; w3 = u3;
            e = en;
        }
    }
    for (; e < e1; ++e) {
        int s = __ldg(&g_csrc[e]);
        float wt = __ldg(&g_cw[e]);
        float4 hs = h4tof4(*(const uint2*)(a16 + (size_t)s * DD + col));
        a0.x += wt * hs.x; a0.y += wt * hs.y; a0.z += wt * hs.z; a0.w += wt * hs.w;
    }
    a0.x += a1.x + a2.x + a3.x;
    a0.y += a1.y + a2.y + a3.y;
    a0.z += a1.z + a2.z + a3.z;
    a0.w += a1.w + a2.w + a3.w;
    *(uint2*)(xa16 + (size_t)w * DD + col) = f4toh4(a0.x, a0.y, a0.z, a0.w);
}

// ======================= fp16 MMA GEMM, register LN, no C-smem (R10) =======================
#define TILE_M 64
#define A_RSH 136
#define A_RSB 272
#define B_RSH 144
#define A_BYTES (TILE_M * A_RSB)  // 17408
#define B_BYTES (128 * B_RSH * 2) // 36864
#define DYN_SMEM (A_BYTES + B_BYTES)
#define TILES ((NN + TILE_M - 1) / TILE_M)

__global__ void __launch_bounds__(256) k_gemm(
    const __half* __restrict__ A16, const __half* __restrict__ Wt16,
    const float* __restrict__ bias, const float* __restrict__ gamma,
    const float* __restrict__ beta,
    const __half* __restrict__ xres16, __half* __restrict__ y16) {
    extern __shared__ char smem[];
    __half* As = (__half*)smem;                 // A tile; reused as fp16 out staging
    __half* Bs = (__half*)(smem + A_BYTES);
    __shared__ float s_b[128], s_g[128], s_be[128];
    __shared__ float s_sum[64][4], s_sq[64][4];

    int tid = threadIdx.x;
    int wid = tid >> 5;
    int lane = tid & 31;
    int m0 = blockIdx.x * TILE_M;
    uint32_t a_base = (uint32_t)__cvta_generic_to_shared(As);

    if (tid < 128) { s_b[tid] = bias[tid]; s_g[tid] = gamma[tid]; s_be[tid] = beta[tid]; }
    for (int i = tid; i < 128 * B_RSH / 8; i += 256)
        ((uint4*)Bs)[i] = ((const uint4*)Wt16)[i];
    for (int i = tid; i < TILE_M * 16; i += 256) {
        int m = i >> 4;
        int ch = i & 15;
        int gm = m0 + m;
        uint4 raw = (gm < NN) ? *(const uint4*)(A16 + (size_t)gm * DD + ch * 8)
                              : make_uint4(0, 0, 0, 0);
        *(uint4*)(As + m * A_RSH + ch * 8) = raw;
    }
    __syncthreads();

    const int wm = (wid >> 2) * 32;
    const int wn = (wid & 3) * 32;
    const int qrow = lane >> 2;
    const int qcol = lane & 3;

    float c[2][4][4];
#pragma unroll
    for (int mt = 0; mt < 2; ++mt)
#pragma unroll
        for (int nt = 0; nt < 4; ++nt)
#pragma unroll
            for (int j = 0; j < 4; ++j) c[mt][nt][j] = 0.f;

#pragma unroll
    for (int ks = 0; ks < 8; ++ks) {
        uint32_t a[2][4], b[4][2];
#pragma unroll
        for (int mt = 0; mt < 2; ++mt) {
            uint32_t addr = a_base + (wm + mt * 16 + (lane & 15)) * A_RSB
                          + ks * 32 + ((lane >> 4) << 4);
            ldmatrix_x4(a[mt][0], a[mt][1], a[mt][2], a[mt][3], addr);
        }
#pragma unroll
        for (int nt = 0; nt < 4; ++nt) {
            int n = wn + nt * 8 + qrow;
            uint2 bb = *(const uint2*)(Bs + n * B_RSH + ks * 16 + qcol * 4);
            b[nt][0] = bb.x; b[nt][1] = bb.y;
        }
#pragma unroll
        for (int mt = 0; mt < 2; ++mt)
#pragma unroll
            for (int nt = 0; nt < 4; ++nt)
                mma_f16(c[mt][nt], a[mt], b[nt]);
    }

    float rsum[4] = {0.f, 0.f, 0.f, 0.f};
    float rsq[4] = {0.f, 0.f, 0.f, 0.f};
#pragma unroll
    for (int mt = 0; mt < 2; ++mt)
#pragma unroll
        for (int nt = 0; nt < 4; ++nt) {
            float2 bv = *(const float2*)&s_b[wn + nt * 8 + qcol * 2];
            c[mt][nt][0] += bv.x; c[mt][nt][1] += bv.y;
            c[mt][nt][2] += bv.x; c[mt][nt][3] += bv.y;
            rsum[mt * 2 + 0] += c[mt][nt][0] + c[mt][nt][1];
            rsum[mt * 2 + 1] += c[mt][nt][2] + c[mt][nt][3];
            rsq[mt * 2 + 0] += c[mt][nt][0] * c[mt][nt][0] + c[mt][nt][1] * c[mt][nt][1];
            rsq[mt * 2 + 1] += c[mt][nt][2] * c[mt][nt][2] + c[mt][nt][3] * c[mt][nt][3];
        }
#pragma unroll
    for (int j = 0; j < 4; ++j) {
        rsum[j] += __shfl_xor_sync(0xffffffffu, rsum[j], 1);
        rsum[j] += __shfl_xor_sync(0xffffffffu, rsum[j], 2);
        rsq[j] += __shfl_xor_sync(0xffffffffu, rsq[j], 1);
        rsq[j] += __shfl_xor_sync(0xffffffffu, rsq[j], 2);
    }
    if (qcol == 0) {
#pragma unroll
        for (int j = 0; j < 4; ++j) {
            int r = wm + (j >> 1) * 16 + (j & 1) * 8 + qrow;
            s_sum[r][wid & 3] = rsum[j];
            s_sq[r][wid & 3] = rsq[j];
        }
    }
    __syncthreads();   // stats ready; MMA A-reads done -> As reusable

    float mu[4], rstd[4];
#pragma unroll
    for (int j = 0; j < 4; ++j) {
        int r = wm + (j >> 1) * 16 + (j & 1) * 8 + qrow;
        float4 ps = *(const float4*)&s_sum[r][0];
        float4 qs = *(const float4*)&s_sq[r][0];
        float sm = ps.x + ps.y + ps.z + ps.w;
        float sq = qs.x + qs.y + qs.z + qs.w;
        mu[j] = sm * (1.f / 128.f);
        float var = sq * (1.f / 128.f) - mu[j] * mu[j];
        rstd[j] = rsqrtf(var + 1e-5f);
    }

#pragma unroll
    for (int mt = 0; mt < 2; ++mt)
#pragma unroll
        for (int half = 0; half < 2; ++half) {
            int j = mt * 2 + half;
            int r = wm + mt * 16 + half * 8 + qrow;
            int row = m0 + r;
            bool ok = (row < NN);
#pragma unroll
            for (int nt = 0; nt < 4; ++nt) {
                int col = wn + nt * 8 + qcol * 2;
                float2 gv = *(const float2*)&s_g[col];
                float2 bev = *(const float2*)&s_be[col];
                float2 xf = make_float2(0.f, 0.f);
                if (ok) {
                    __half2 xr = *(const __half2*)(xres16 + (size_t)row * DD + col);
                    xf = __half22float2(xr);
                }
                float v0 = (c[mt][nt][half * 2 + 0] - mu[j]) * rstd[j] * gv.x + bev.x + xf.x;
                float v1 = (c[mt][nt][half * 2 + 1] - mu[j]) * rstd[j] * gv.y + bev.y + xf.y;
                v0 = v0 / (1.f + __expf(-v0));
                v1 = v1 / (1.f + __expf(-v1));
                *(__half2*)(As + r * A_RSH + col) = __floats2half2_rn(v0, v1);
            }
        }
    __syncthreads();

    for (int i = tid; i < TILE_M * 16; i += 256) {
        int m = i >> 4;
        int ch = i & 15;
        int row = m0 + m;
        if (row < NN)
            *(uint4*)(y16 + (size_t)row * DD + ch * 8) = *(const uint4*)(As + m * A_RSH + ch * 8);
    }
}

// ======================= global mean pool (fp16 input) =======================
__device__ __forceinline__ int lowerb(const int* __restrict__ a, int n, int key) {
    int lo = 0, hi = n;
    while (lo < hi) {
        int mid = (lo + hi) >> 1;
        if (a[mid] < key) lo = mid + 1; else hi = mid;
    }
    return lo;
}
__global__ void __launch_bounds__(1024) k_pool(const __half* __restrict__ x,
                                               const int* __restrict__ batch,
                                               float* __restrict__ out) {
    __shared__ int sl, sh;
    __shared__ float part[8][128];
    int g = blockIdx.x;
    if (threadIdx.x == 0) {
        sl = lowerb(batch, NN, g);
        sh = lowerb(batch, NN, g + 1);
    }
    __syncthreads();
    int lo = sl, hi = sh;
    int c = threadIdx.x & 127;
    int rchunk = threadIdx.x >> 7;
    float s0 = 0.f, s1 = 0.f;
    int n = lo + rchunk;
    for (; n + 8 < hi; n += 16) {
        s0 += __half2float(x[(size_t)n * DD + c]);
        s1 += __half2float(x[(size_t)(n + 8) * DD + c]);
    }
    if (n < hi) s0 += __half2float(x[(size_t)n * DD + c]);
    part[rchunk][c] = s0 + s1;
    __syncthreads();
    if (rchunk == 0) {
        float t = 0.f;
#pragma unroll
        for (int j = 0; j < 8; ++j) t += part[j][c];
        out[g * DD + c] = t / fmaxf((float)(hi - lo), 1.f);
    }
}

// ======================= launch =======================
extern "C" void kernel_launch(void* const* d_in, const int* in_sizes, int n_in,
                              void* d_out, int out_size) {
    const float* x     = (const float*)d_in[0];
    const int*   ei    = (const int*)d_in[1];
    const int*   batch = (const int*)d_in[2];
    const float* W[3]  = {(const float*)d_in[3],  (const float*)d_in[7],  (const float*)d_in[11]};
    const float* b[3]  = {(const float*)d_in[4],  (const float*)d_in[8],  (const float*)d_in[12]};
    const float* g[3]  = {(const float*)d_in[5],  (const float*)d_in[9],  (const float*)d_in[13]};
    const float* be[3] = {(const float*)d_in[6],  (const float*)d_in[10], (const float*)d_in[14]};
    float* out = (float*)d_out;

    __half *x16 = nullptr, *h0 = nullptr, *h1 = nullptr, *h2 = nullptr, *xa16 = nullptr, *wt16 = nullptr;
    int* pdeg = nullptr;
    cudaGetSymbolAddress((void**)&x16, g_x16);
    cudaGetSymbolAddress((void**)&h0, g_h0);
    cudaGetSymbolAddress((void**)&h1, g_h1);
    cudaGetSymbolAddress((void**)&h2, g_h2);
    cudaGetSymbolAddress((void**)&xa16, g_xa16);
    cudaGetSymbolAddress((void**)&wt16, g_wt16);
    cudaGetSymbolAddress((void**)&pdeg, g_deg);

    cudaFuncSetAttribute(k_gemm, cudaFuncAttributeMaxDynamicSharedMemorySize, DYN_SMEM);

    cudaMemsetAsync(pdeg, 0, NN * sizeof(int));
    k_deg_x16<<<DEGB + CVTB, 256>>>(ei, x);
    k_scan_wt<<<4, 1024>>>(W[0], W[1], W[2]);
    k_fill<<<(EE + 255) / 256, 256>>>(ei);

    const int agg_blocks = (NN * 32 + 255) / 256;   // one warp per node

    k_agg<<<agg_blocks, 256>>>(x16, xa16);
    k_gemm<<<TILES, 256, DYN_SMEM>>>(xa16, wt16 + 0 * DD * 144, b[0], g[0], be[0], x16, h0);
    k_agg<<<agg_blocks, 256>>>(h0, xa16);
    k_gemm<<<TILES, 256, DYN_SMEM>>>(xa16, wt16 + 1 * DD * 144, b[1], g[1], be[1], h0, h1);
    k_agg<<<agg_blocks, 256>>>(h1, xa16);
    k_gemm<<<TILES, 256, DYN_SMEM>>>(xa16, wt16 + 2 * DD * 144, b[2], g[2], be[2], h1, h2);

    k_pool<<<GG, 1024>>>(h2, batch, out);
}

// round 14
// speedup vs baseline: 1.5979x; 1.5979x over previous
#include <cuda_runtime.h>
#include <cuda_fp16.h>
#include <cstdint>
#include <math.h>

#define NN 50000
#define EE 600000
#define DD 128
#define GG 128

// ---------------- device scratch ----------------
__device__ __half g_x16[NN * DD];      // fp16 input x (L0 gather + residual)
__device__ __half g_h0[NN * DD];       // L0 out
__device__ __half g_h1[NN * DD];       // L1 out
__device__ __half g_h2[NN * DD];       // L2 out (pool input)
__device__ __half g_xa16[NN * DD];     // aggregation scratch
__device__ int    g_deg[NN];
__device__ int    g_rank[EE];
__device__ float  g_dinv[NN];
__device__ int    g_rowptr[NN + 1];
__device__ int    g_csrc[EE];
__device__ float  g_cw[EE];
__device__ __half g_wt16[3][DD * 144]; // W^T fp16, row stride 144, perm16 k-layout

__device__ __forceinline__ float4 h4tof4(uint2 raw) {
    __half2 h0 = *(__half2*)&raw.x;
    __half2 h1 = *(__half2*)&raw.y;
    float2 f0 = __half22float2(h0);
    float2 f1 = __half22float2(h1);
    return make_float4(f0.x, f0.y, f1.x, f1.y);
}
__device__ __forceinline__ uint2 f4toh4(float a, float b, float c, float d) {
    __half2 p0 = __floats2half2_rn(a, b);
    __half2 p1 = __floats2half2_rn(c, d);
    uint2 st;
    st.x = *(uint32_t*)&p0;
    st.y = *(uint32_t*)&p1;
    return st;
}
__device__ __forceinline__ void ldmatrix_x4(uint32_t& r0, uint32_t& r1,
                                            uint32_t& r2, uint32_t& r3, uint32_t addr) {
    asm volatile("ldmatrix.sync.aligned.m8n8.x4.shared.b16 {%0,%1,%2,%3}, [%4];"
                 : "=r"(r0), "=r"(r1), "=r"(r2), "=r"(r3) : "r"(addr));
}
__device__ __forceinline__ void mma_f16(float c[4], const uint32_t a[4], const uint32_t b[2]) {
    asm volatile(
        "mma.sync.aligned.m16n8k16.row.col.f32.f16.f16.f32 "
        "{%0,%1,%2,%3}, {%4,%5,%6,%7}, {%8,%9}, {%0,%1,%2,%3};"
        : "+f"(c[0]), "+f"(c[1]), "+f"(c[2]), "+f"(c[3])
        : "r"(a[0]), "r"(a[1]), "r"(a[2]), "r"(a[3]), "r"(b[0]), "r"(b[1]));
}

// ======================= deg + x->fp16 convert =======================
#define DEGB ((EE + 255) / 256)
#define CVTB ((NN * DD / 8 + 255) / 256)

__global__ void k_deg_x16(const int* __restrict__ ei, const float* __restrict__ x) {
    if (blockIdx.x < DEGB) {
        int e = blockIdx.x * 256 + threadIdx.x;
        if (e < EE) g_rank[e] = atomicAdd(&g_deg[ei[EE + e]], 1);
    } else {
        int i = (blockIdx.x - DEGB) * 256 + threadIdx.x;
        if (i < NN * DD / 8) {
            float4 v0 = *(const float4*)(x + (size_t)i * 8);
            float4 v1 = *(const float4*)(x + (size_t)i * 8 + 4);
            uint2 a = f4toh4(v0.x, v0.y, v0.z, v0.w);
            uint2 b = f4toh4(v1.x, v1.y, v1.z, v1.w);
            *(uint4*)(g_x16 + (size_t)i * 8) = make_uint4(a.x, a.y, b.x, b.y);
        }
    }
}

// ======================= scan + dinv + W^T fp16 precompute =======================
__global__ void k_scan_wt(const float* __restrict__ W0, const float* __restrict__ W1,
                          const float* __restrict__ W2) {
    if (blockIdx.x > 0) {
        const float* Ws[3] = {W0, W1, W2};
        int l = blockIdx.x - 1;
        for (int i = threadIdx.x; i < DD * 144; i += 1024) {
            int n = i / 144;
            int j = i % 144;
            __half v = __float2half(0.f);
            if (j < 128) {
                int grp = j >> 4, w = j & 15;
                int k = grp * 16 + ((w >> 1) & 1) * 8 + (w >> 2) * 2 + (w & 1);
                v = __float2half(Ws[l][(size_t)k * DD + n]);
            }
            g_wt16[l][i] = v;
        }
        return;
    }
    const int CH = (NN + 1023) / 1024;
    __shared__ int ss[1024];
    int t = threadIdx.x;
    int vals[CH];
    int base = t * CH;
    int loc = 0;
#pragma unroll
    for (int i = 0; i < CH; ++i) {
        int idx = base + i;
        int v = (idx < NN) ? g_deg[idx] : 0;
        if (idx < NN) g_dinv[idx] = rsqrtf((float)(v + 1));
        vals[i] = loc;
        loc += v;
    }
    ss[t] = loc;
    __syncthreads();
    for (int off = 1; off < 1024; off <<= 1) {
        int v = (t >= off) ? ss[t - off] : 0;
        __syncthreads();
        ss[t] += v;
        __syncthreads();
    }
    int pre = (t > 0) ? ss[t - 1] : 0;
#pragma unroll
    for (int i = 0; i < CH; ++i) {
        int idx = base + i;
        if (idx < NN) g_rowptr[idx] = pre + vals[i];
    }
    if (t == 1023) g_rowptr[NN] = ss[1023];
}

__global__ void k_fill(const int* __restrict__ ei) {
    int e = blockIdx.x * blockDim.x + threadIdx.x;
    if (e < EE) {
        int s = ei[e];
        int d = ei[EE + e];
        int pos = g_rowptr[d] + g_rank[e];
        g_csrc[pos] = s;
        g_cw[pos] = g_dinv[s] * g_dinv[d];
    }
}

// ======================= aggregation: one warp per node (R10 shape — DO NOT TOUCH) =======================
__global__ void __launch_bounds__(256) k_agg(const __half* __restrict__ a16,
                                             __half* __restrict__ xa16) {
    int w = (blockIdx.x * blockDim.x + threadIdx.x) >> 5;
    int lane = threadIdx.x & 31;
    if (w >= NN) return;
    int col = lane * 4;

    float di = g_dinv[w];
    float sw = di * di;
    float4 a0 = h4tof4(*(const uint2*)(a16 + (size_t)w * DD + col));
    a0.x *= sw; a0.y *= sw; a0.z *= sw; a0.w *= sw;
    float4 a1 = make_float4(0.f, 0.f, 0.f, 0.f);
    float4 a2 = a1, a3 = a1;

    int e0 = g_rowptr[w], e1 = g_rowptr[w + 1];
    int e = e0;
    for (; e + 4 <= e1; e += 4) {
        int s0 = __ldg(&g_csrc[e + 0]);
        int s1 = __ldg(&g_csrc[e + 1]);
        int s2 = __ldg(&g_csrc[e + 2]);
        int s3 = __ldg(&g_csrc[e + 3]);
        float w0 = __ldg(&g_cw[e + 0]);
        float w1 = __ldg(&g_cw[e + 1]);
        float w2 = __ldg(&g_cw[e + 2]);
        float w3 = __ldg(&g_cw[e + 3]);
        float4 h0 = h4tof4(*(const uint2*)(a16 + (size_t)s0 * DD + col));
        float4 h1 = h4tof4(*(const uint2*)(a16 + (size_t)s1 * DD + col));
        float4 h2 = h4tof4(*(const uint2*)(a16 + (size_t)s2 * DD + col));
        float4 h3 = h4tof4(*(const uint2*)(a16 + (size_t)s3 * DD + col));
        a0.x += w0 * h0.x; a0.y += w0 * h0.y; a0.z += w0 * h0.z; a0.w += w0 * h0.w;
        a1.x += w1 * h1.x; a1.y += w1 * h1.y; a1.z += w1 * h1.z; a1.w += w1 * h1.w;
        a2.x += w2 * h2.x; a2.y += w2 * h2.y; a2.z += w2 * h2.z; a2.w += w2 * h2.w;
        a3.x += w3 * h3.x; a3.y += w3 * h3.y; a3.z += w3 * h3.z; a3.w += w3 * h3.w;
    }
    for (; e < e1; ++e) {
        int s = __ldg(&g_csrc[e]);
        float wt = __ldg(&g_cw[e]);
        float4 hs = h4tof4(*(const uint2*)(a16 + (size_t)s * DD + col));
        a0.x += wt * hs.x; a0.y += wt * hs.y; a0.z += wt * hs.z; a0.w += wt * hs.w;
    }
    a0.x += a1.x + a2.x + a3.x;
    a0.y += a1.y + a2.y + a3.y;
    a0.z += a1.z + a2.z + a3.z;
    a0.w += a1.w + a2.w + a3.w;
    *(uint2*)(xa16 + (size_t)w * DD + col) = f4toh4(a0.x, a0.y, a0.z, a0.w);
}

// ======================= fp16 MMA GEMM, register LN, no C-smem; 3 CTAs/SM =======================
#define TILE_M 64
#define A_RSH 136
#define A_RSB 272
#define B_RSH 144
#define A_BYTES (TILE_M * A_RSB)  // 17408
#define B_BYTES (128 * B_RSH * 2) // 36864
#define DYN_SMEM (A_BYTES + B_BYTES)
#define TILES ((NN + TILE_M - 1) / TILE_M)

__global__ void __launch_bounds__(256, 3) k_gemm(
    const __half* __restrict__ A16, const __half* __restrict__ Wt16,
    const float* __restrict__ bias, const float* __restrict__ gamma,
    const float* __restrict__ beta,
    const __half* __restrict__ xres16, __half* __restrict__ y16) {
    extern __shared__ char smem[];
    __half* As = (__half*)smem;                 // A tile; reused as fp16 out staging
    __half* Bs = (__half*)(smem + A_BYTES);
    __shared__ float s_b[128], s_g[128], s_be[128];
    __shared__ float s_sum[64][4], s_sq[64][4];

    int tid = threadIdx.x;
    int wid = tid >> 5;
    int lane = tid & 31;
    int m0 = blockIdx.x * TILE_M;
    uint32_t a_base = (uint32_t)__cvta_generic_to_shared(As);

    if (tid < 128) { s_b[tid] = bias[tid]; s_g[tid] = gamma[tid]; s_be[tid] = beta[tid]; }
    for (int i = tid; i < 128 * B_RSH / 8; i += 256)
        ((uint4*)Bs)[i] = ((const uint4*)Wt16)[i];
    for (int i = tid; i < TILE_M * 16; i += 256) {
        int m = i >> 4;
        int ch = i & 15;
        int gm = m0 + m;
        uint4 raw = (gm < NN) ? *(const uint4*)(A16 + (size_t)gm * DD + ch * 8)
                              : make_uint4(0, 0, 0, 0);
        *(uint4*)(As + m * A_RSH + ch * 8) = raw;
    }
    __syncthreads();

    const int wm = (wid >> 2) * 32;
    const int wn = (wid & 3) * 32;
    const int qrow = lane >> 2;
    const int qcol = lane & 3;

    float c[2][4][4];
#pragma unroll
    for (int mt = 0; mt < 2; ++mt)
#pragma unroll
        for (int nt = 0; nt < 4; ++nt)
#pragma unroll
            for (int j = 0; j < 4; ++j) c[mt][nt][j] = 0.f;

#pragma unroll
    for (int ks = 0; ks < 8; ++ks) {
        uint32_t a[2][4], b[4][2];
#pragma unroll
        for (int mt = 0; mt < 2; ++mt) {
            uint32_t addr = a_base + (wm + mt * 16 + (lane & 15)) * A_RSB
                          + ks * 32 + ((lane >> 4) << 4);
            ldmatrix_x4(a[mt][0], a[mt][1], a[mt][2], a[mt][3], addr);
        }
#pragma unroll
        for (int nt = 0; nt < 4; ++nt) {
            int n = wn + nt * 8 + qrow;
            uint2 bb = *(const uint2*)(Bs + n * B_RSH + ks * 16 + qcol * 4);
            b[nt][0] = bb.x; b[nt][1] = bb.y;
        }
#pragma unroll
        for (int mt = 0; mt < 2; ++mt)
#pragma unroll
            for (int nt = 0; nt < 4; ++nt)
                mma_f16(c[mt][nt], a[mt], b[nt]);
    }

    float rsum[4] = {0.f, 0.f, 0.f, 0.f};
    float rsq[4] = {0.f, 0.f, 0.f, 0.f};
#pragma unroll
    for (int mt = 0; mt < 2; ++mt)
#pragma unroll
        for (int nt = 0; nt < 4; ++nt) {
            float2 bv = *(const float2*)&s_b[wn + nt * 8 + qcol * 2];
            c[mt][nt][0] += bv.x; c[mt][nt][1] += bv.y;
            c[mt][nt][2] += bv.x; c[mt][nt][3] += bv.y;
            rsum[mt * 2 + 0] += c[mt][nt][0] + c[mt][nt][1];
            rsum[mt * 2 + 1] += c[mt][nt][2] + c[mt][nt][3];
            rsq[mt * 2 + 0] += c[mt][nt][0] * c[mt][nt][0] + c[mt][nt][1] * c[mt][nt][1];
            rsq[mt * 2 + 1] += c[mt][nt][2] * c[mt][nt][2] + c[mt][nt][3] * c[mt][nt][3];
        }
#pragma unroll
    for (int j = 0; j < 4; ++j) {
        rsum[j] += __shfl_xor_sync(0xffffffffu, rsum[j], 1);
        rsum[j] += __shfl_xor_sync(0xffffffffu, rsum[j], 2);
        rsq[j] += __shfl_xor_sync(0xffffffffu, rsq[j], 1);
        rsq[j] += __shfl_xor_sync(0xffffffffu, rsq[j], 2);
    }
    if (qcol == 0) {
#pragma unroll
        for (int j = 0; j < 4; ++j) {
            int r = wm + (j >> 1) * 16 + (j & 1) * 8 + qrow;
            s_sum[r][wid & 3] = rsum[j];
            s_sq[r][wid & 3] = rsq[j];
        }
    }
    __syncthreads();   // stats ready; MMA A-reads done -> As reusable

    float mu[4], rstd[4];
#pragma unroll
    for (int j = 0; j < 4; ++j) {
        int r = wm + (j >> 1) * 16 + (j & 1) * 8 + qrow;
        float4 ps = *(const float4*)&s_sum[r][0];
        float4 qs = *(const float4*)&s_sq[r][0];
        float sm = ps.x + ps.y + ps.z + ps.w;
        float sq = qs.x + qs.y + qs.z + qs.w;
        mu[j] = sm * (1.f / 128.f);
        float var = sq * (1.f / 128.f) - mu[j] * mu[j];
        rstd[j] = rsqrtf(var + 1e-5f);
    }

#pragma unroll
    for (int mt = 0; mt < 2; ++mt)
#pragma unroll
        for (int half = 0; half < 2; ++half) {
            int j = mt * 2 + half;
            int r = wm + mt * 16 + half * 8 + qrow;
            int row = m0 + r;
            bool ok = (row < NN);
#pragma unroll
            for (int nt = 0; nt < 4; ++nt) {
                int col = wn + nt * 8 + qcol * 2;
                float2 gv = *(const float2*)&s_g[col];
                float2 bev = *(const float2*)&s_be[col];
                float2 xf = make_float2(0.f, 0.f);
                if (ok) {
                    __half2 xr = *(const __half2*)(xres16 + (size_t)row * DD + col);
                    xf = __half22float2(xr);
                }
                float v0 = (c[mt][nt][half * 2 + 0] - mu[j]) * rstd[j] * gv.x + bev.x + xf.x;
                float v1 = (c[mt][nt][half * 2 + 1] - mu[j]) * rstd[j] * gv.y + bev.y + xf.y;
                v0 = v0 / (1.f + __expf(-v0));
                v1 = v1 / (1.f + __expf(-v1));
                *(__half2*)(As + r * A_RSH + col) = __floats2half2_rn(v0, v1);
            }
        }
    __syncthreads();

    for (int i = tid; i < TILE_M * 16; i += 256) {
        int m = i >> 4;
        int ch = i & 15;
        int row = m0 + m;
        if (row < NN)
            *(uint4*)(y16 + (size_t)row * DD + ch * 8) = *(const uint4*)(As + m * A_RSH + ch * 8);
    }
}

// ======================= global mean pool (fp16 input) =======================
__device__ __forceinline__ int lowerb(const int* __restrict__ a, int n, int key) {
    int lo = 0, hi = n;
    while (lo < hi) {
        int mid = (lo + hi) >> 1;
        if (a[mid] < key) lo = mid + 1; else hi = mid;
    }
    return lo;
}
__global__ void __launch_bounds__(1024) k_pool(const __half* __restrict__ x,
                                               const int* __restrict__ batch,
                                               float* __restrict__ out) {
    __shared__ int sl, sh;
    __shared__ float part[8][128];
    int g = blockIdx.x;
    if (threadIdx.x == 0) {
        sl = lowerb(batch, NN, g);
        sh = lowerb(batch, NN, g + 1);
    }
    __syncthreads();
    int lo = sl, hi = sh;
    int c = threadIdx.x & 127;
    int rchunk = threadIdx.x >> 7;
    float s0 = 0.f, s1 = 0.f;
    int n = lo + rchunk;
    for (; n + 8 < hi; n += 16) {
        s0 += __half2float(x[(size_t)n * DD + c]);
        s1 += __half2float(x[(size_t)(n + 8) * DD + c]);
    }
    if (n < hi) s0 += __half2float(x[(size_t)n * DD + c]);
    part[rchunk][c] = s0 + s1;
    __syncthreads();
    if (rchunk == 0) {
        float t = 0.f;
#pragma unroll
        for (int j = 0; j < 8; ++j) t += part[j][c];
        out[g * DD + c] = t / fmaxf((float)(hi - lo), 1.f);
    }
}

// ======================= launch =======================
extern "C" void kernel_launch(void* const* d_in, const int* in_sizes, int n_in,
                              void* d_out, int out_size) {
    const float* x     = (const float*)d_in[0];
    const int*   ei    = (const int*)d_in[1];
    const int*   batch = (const int*)d_in[2];
    const float* W[3]  = {(const float*)d_in[3],  (const float*)d_in[7],  (const float*)d_in[11]};
    const float* b[3]  = {(const float*)d_in[4],  (const float*)d_in[8],  (const float*)d_in[12]};
    const float* g[3]  = {(const float*)d_in[5],  (const float*)d_in[9],  (const float*)d_in[13]};
    const float* be[3] = {(const float*)d_in[6],  (const float*)d_in[10], (const float*)d_in[14]};
    float* out = (float*)d_out;

    __half *x16 = nullptr, *h0 = nullptr, *h1 = nullptr, *h2 = nullptr, *xa16 = nullptr, *wt16 = nullptr;
    int* pdeg = nullptr;
    cudaGetSymbolAddress((void**)&x16, g_x16);
    cudaGetSymbolAddress((void**)&h0, g_h0);
    cudaGetSymbolAddress((void**)&h1, g_h1);
    cudaGetSymbolAddress((void**)&h2, g_h2);
    cudaGetSymbolAddress((void**)&xa16, g_xa16);
    cudaGetSymbolAddress((void**)&wt16, g_wt16);
    cudaGetSymbolAddress((void**)&pdeg, g_deg);

    cudaFuncSetAttribute(k_gemm, cudaFuncAttributeMaxDynamicSharedMemorySize, DYN_SMEM);

    cudaMemsetAsync(pdeg, 0, NN * sizeof(int));
    k_deg_x16<<<DEGB + CVTB, 256>>>(ei, x);
    k_scan_wt<<<4, 1024>>>(W[0], W[1], W[2]);
    k_fill<<<(EE + 255) / 256, 256>>>(ei);

    const int agg_blocks = (NN * 32 + 255) / 256;   // one warp per node

    k_agg<<<agg_blocks, 256>>>(x16, xa16);
    k_gemm<<<TILES, 256, DYN_SMEM>>>(xa16, wt16 + 0 * DD * 144, b[0], g[0], be[0], x16, h0);
    k_agg<<<agg_blocks, 256>>>(h0, xa16);
    k_gemm<<<TILES, 256, DYN_SMEM>>>(xa16, wt16 + 1 * DD * 144, b[1], g[1], be[1], h0, h1);
    k_agg<<<agg_blocks, 256>>>(h1, xa16);
    k_gemm<<<TILES, 256, DYN_SMEM>>>(xa16, wt16 + 2 * DD * 144, b[2], g[2], be[2], h1, h2);

    k_pool<<<GG, 1024>>>(h2, batch, out);
}